// round 16
// baseline (speedup 1.0000x reference)
#include <cuda_runtime.h>
#include <cuda_fp16.h>
#include <math.h>
#include <stdint.h>

#define BB 4
#define SS 2048
#define DD 1024
#define MT (BB*SS)   // 8192

#define NPERS 304    // persistent CTAs: 2 per SM, 152 SMs on GB300

// ---------------------------------------------------------------------------
// Scratch (device globals) — all operands fp16 hi-plane only
// ---------------------------------------------------------------------------
__device__ __align__(16) __half g_xh [(size_t)MT*DD];                 // A of QKV
__device__ __align__(16) __half g_Wth[(size_t)3*DD*DD];               // B of QKV (transposed)
__device__ __align__(16) __half g_Qh [(size_t)MT*DD];                 // A of scores
__device__ __align__(16) __half g_Kh [(size_t)MT*DD];                 // B of scores
__device__ __align__(16) __half g_Vth[(size_t)BB*DD*SS];              // B of PV
__device__ __align__(16) __half g_Ph [(size_t)BB*SS*SS];              // Pexp (unnormalized)
__device__ __align__(16) float  g_rs [MT];                            // row sums
__device__ unsigned g_tk[3];                                          // work tickets

// ---------------------------------------------------------------------------
// Helpers
// ---------------------------------------------------------------------------
__device__ __forceinline__ uint32_t smem_u32(const void* p) {
    uint32_t a;
    asm("{ .reg .u64 t; cvta.to.shared.u64 t, %1; cvt.u32.u64 %0, t; }"
        : "=r"(a) : "l"(p));
    return a;
}

#define SWZ(o) ((uint32_t)(o) ^ ((((uint32_t)(o)) >> 3) & 0x70))

#define CP_ASYNC(dst, src) \
    asm volatile("cp.async.cg.shared.global [%0], [%1], 16;" \
                 :: "r"(dst), "l"(__cvta_generic_to_global(src)))
#define CP_COMMIT() asm volatile("cp.async.commit_group;")
#define CP_WAIT1()  asm volatile("cp.async.wait_group 1;")
#define CP_WAIT0()  asm volatile("cp.async.wait_group 0;")

#define LDM_X4(r, addr) \
    asm volatile("ldmatrix.sync.aligned.m8n8.x4.shared.b16 {%0,%1,%2,%3}, [%4];" \
        : "=r"((r)[0]), "=r"((r)[1]), "=r"((r)[2]), "=r"((r)[3]) : "r"(addr))

#define MMA_F16(d, a, b0v, b1v) \
    asm volatile("mma.sync.aligned.m16n8k16.row.col.f32.f16.f16.f32 " \
        "{%0,%1,%2,%3}, {%4,%5,%6,%7}, {%8,%9}, {%0,%1,%2,%3};" \
        : "+f"((d)[0]), "+f"((d)[1]), "+f"((d)[2]), "+f"((d)[3]) \
        : "r"((a)[0]), "r"((a)[1]), "r"((a)[2]), "r"((a)[3]), "r"(b0v), "r"(b1v))

__device__ __forceinline__ uint32_t packh2(float a, float b) {
    __half2 h = __floats2half2_rn(a, b);
    return *(uint32_t*)&h;
}

// Ticket broadcast: one atomic per CTA-iteration, broadcast via static smem.
__device__ __forceinline__ unsigned next_ticket(int which, unsigned* s_t, int tid) {
    __syncthreads();                 // prior tile's smem reads done before reuse
    if (tid == 0) *s_t = atomicAdd(&g_tk[which], 1u);
    __syncthreads();
    return *s_t;
}

// ---------------------------------------------------------------------------
// SMEM: 1-term stage = A(16K)+B(16K) = 32KB x 3 stages = 96KB -> 2 CTAs/SM
// ---------------------------------------------------------------------------
#define OFF_A  0
#define OFF1_B 16384
#define STG1   32768
#define SM_TOT 98304

// transpose-staging (epilogue reuse): 128 rows x 130 half = 260B rows
#define TRROW 260
#define TRH   0

// ===========================================================================
// 1-term GEMM: acc += A*B, 3-stage pipeline, warp tile 64x32, CTA 128x128.
// ===========================================================================
__device__ __forceinline__ void load_chunk1(
    uint32_t stg,
    const __half* __restrict__ A, int lda,
    const __half* __restrict__ B, int ldb,
    int k0, int tid)
{
#pragma unroll
    for (int i = 0; i < 4; ++i) {
        int u = tid + i * 256, row = u >> 3, ch = u & 7;
        uint32_t off = SWZ(row * 128 + ch * 16);
        CP_ASYNC(stg + OFF_A  + off, A + (size_t)row * lda + k0 + ch * 8);
        CP_ASYNC(stg + OFF1_B + off, B + (size_t)row * ldb + k0 + ch * 8);
    }
}

__device__ __forceinline__ void compute_chunk1(
    uint32_t stg, int wm, int wn, int lane, float (&acc)[4][4][4])
{
    const int rsel = lane & 15;
    const int csel = lane >> 4;
#pragma unroll
    for (int ks = 0; ks < 4; ++ks) {
        const uint32_t cb = (ks * 2 + csel) * 16;
        uint32_t ah[4][4], bh[2][4];
#pragma unroll
        for (int j2 = 0; j2 < 2; ++j2)
            LDM_X4(bh[j2], stg + OFF1_B + SWZ((wn * 32 + j2 * 16 + rsel) * 128 + cb));
#pragma unroll
        for (int i = 0; i < 4; ++i)
            LDM_X4(ah[i], stg + OFF_A + SWZ((wm * 64 + i * 16 + rsel) * 128 + cb));
#pragma unroll
        for (int i = 0; i < 4; ++i)
#pragma unroll
            for (int j = 0; j < 4; ++j)
                MMA_F16(acc[i][j], ah[i], bh[j >> 1][j & 1], bh[j >> 1][(j & 1) + 2]);
    }
}

template <int NCH>
__device__ __forceinline__ void gemm_1t_fixed(
    const __half* __restrict__ A, int lda,
    const __half* __restrict__ B, int ldb,
    float (&acc)[4][4][4], uint32_t sb, int tid)
{
    const int lane = tid & 31, w = tid >> 5;
    const int wm = w & 1, wn = w >> 1;

#pragma unroll
    for (int i = 0; i < 4; ++i)
#pragma unroll
        for (int j = 0; j < 4; ++j)
#pragma unroll
            for (int q = 0; q < 4; ++q) acc[i][j][q] = 0.f;

    load_chunk1(sb + 0 * STG1, A, lda, B, ldb, 0, tid);
    CP_COMMIT();
    load_chunk1(sb + 1 * STG1, A, lda, B, ldb, 64, tid);
    CP_COMMIT();

#pragma unroll
    for (int c = 0; c < NCH; ++c) {
        if (c + 1 < NCH) { CP_WAIT1(); } else { CP_WAIT0(); }
        __syncthreads();
        if (c + 2 < NCH) {
            const int ns = (c + 2) % 3;
            load_chunk1(sb + ns * STG1, A, lda, B, ldb, (c + 2) * 64, tid);
            CP_COMMIT();
        }
        compute_chunk1(sb + (c % 3) * STG1, wm, wn, lane, acc);
    }
}

__device__ __forceinline__ void gemm_1t(
    const __half* __restrict__ A, int lda,
    const __half* __restrict__ B, int ldb,
    int nCh, float (&acc)[4][4][4], uint32_t sb, int tid)
{
    const int lane = tid & 31, w = tid >> 5;
    const int wm = w & 1, wn = w >> 1;

#pragma unroll
    for (int i = 0; i < 4; ++i)
#pragma unroll
        for (int j = 0; j < 4; ++j)
#pragma unroll
            for (int q = 0; q < 4; ++q) acc[i][j][q] = 0.f;

    load_chunk1(sb + 0 * STG1, A, lda, B, ldb, 0, tid);
    CP_COMMIT();
    load_chunk1(sb + 1 * STG1, A, lda, B, ldb, 64, tid);
    CP_COMMIT();

    int slot = 0;
    for (int c = 0; c < nCh; ++c) {
        if (c + 1 < nCh) { CP_WAIT1(); } else { CP_WAIT0(); }
        __syncthreads();
        if (c + 2 < nCh) {
            int ns = slot + 2; if (ns >= 3) ns -= 3;
            load_chunk1(sb + ns * STG1, A, lda, B, ldb, (c + 2) * 64, tid);
            CP_COMMIT();
        }
        compute_chunk1(sb + slot * STG1, wm, wn, lane, acc);
        if (++slot == 3) slot = 0;
    }
}

// ---------------------------------------------------------------------------
// 1) QKV GEMM, persistent: tickets 0..1535 -> (z, m0, n0).
//    z=0->Q, z=1->K, z=2->V transposed (fused via smem). grid NPERS
// ---------------------------------------------------------------------------
__global__ void __launch_bounds__(256, 2) qkv_gemm()
{
    extern __shared__ char smem[];
    __shared__ unsigned s_t;
    const uint32_t sb = smem_u32(smem);
    const int tid = threadIdx.x, lane = tid & 31, w = tid >> 5;
    const int tg = lane >> 2, t4 = lane & 3;
    const int wm = w & 1, wn = w >> 1;

    for (;;) {
        const unsigned t = next_ticket(0, &s_t, tid);
        if (t >= 1536u) return;
        const int z  = t >> 9;           // t / 512
        const int rm = t & 511;
        const int m0 = (rm >> 3) * 128;
        const int n0 = (rm & 7) * 128;

        float acc[4][4][4];
        gemm_1t_fixed<16>(g_xh + (size_t)m0 * DD, DD,
                          g_Wth + (size_t)z * DD * DD + (size_t)n0 * DD, DD,
                          acc, sb, tid);

        if (z == 2) {
            // Fused V transpose (hi plane only).
            __syncthreads();
#pragma unroll
            for (int i = 0; i < 4; ++i) {
#pragma unroll
                for (int j = 0; j < 4; ++j) {
                    const int rl = wm * 64 + i * 16 + tg;
                    const int cl = wn * 32 + j * 8 + t4 * 2;
                    *(uint32_t*)(smem + TRH + rl * TRROW + cl * 2) =
                        packh2(acc[i][j][0], acc[i][j][1]);
                    *(uint32_t*)(smem + TRH + (rl + 8) * TRROW + cl * 2) =
                        packh2(acc[i][j][2], acc[i][j][3]);
                }
            }
            __syncthreads();
            const int b = m0 >> 11, s0r = m0 & 2047;
            const int d = tid >> 1, sh = tid & 1;
            __half* dstH = g_Vth + ((size_t)b * DD + n0 + d) * SS + s0r + sh * 64;
#pragma unroll
            for (int g = 0; g < 8; ++g) {
                uint32_t wh[4];
#pragma unroll
                for (int e = 0; e < 4; ++e) {
                    const int s = sh * 64 + g * 8 + e * 2;
                    uint32_t h0 = *(uint16_t*)(smem + TRH + s * TRROW + d * 2);
                    uint32_t h1 = *(uint16_t*)(smem + TRH + (s + 1) * TRROW + d * 2);
                    wh[e] = h0 | (h1 << 16);
                }
                *(uint4*)(dstH + g * 8) = make_uint4(wh[0], wh[1], wh[2], wh[3]);
            }
            continue;
        }

        __half* dst = (z == 0) ? g_Qh : g_Kh;
#pragma unroll
        for (int i = 0; i < 4; ++i) {
#pragma unroll
            for (int j = 0; j < 4; ++j) {
                const int r = m0 + wm * 64 + i * 16 + tg;
                const int c = n0 + wn * 32 + j * 8 + t4 * 2;
                *(uint32_t*)(dst + (size_t)r * DD + c) =
                    packh2(acc[i][j][0], acc[i][j][1]);
                *(uint32_t*)(dst + (size_t)(r + 8) * DD + c) =
                    packh2(acc[i][j][2], acc[i][j][3]);
            }
        }
    }
}

// ---------------------------------------------------------------------------
// 2) Scores+exp, persistent: tickets 0..543; b = tk/136, tt = tk%136 ->
//    triangular (it, jt). Pexp = exp(scale*Q@K^T), fp16 out, row-sum atomics.
//    grid NPERS
// ---------------------------------------------------------------------------
__global__ void __launch_bounds__(256, 2) scores_gemm()
{
    extern __shared__ char smem[];
    __shared__ unsigned s_t;
    const uint32_t sb = smem_u32(smem);
    const int tid = threadIdx.x, lane = tid & 31, w = tid >> 5;
    const int tg = lane >> 2, t4 = lane & 3;
    const int wm = w & 1, wn = w >> 1;
    const float scale = 0.03125f;  // 1/sqrt(1024)

    for (;;) {
        const unsigned tk = next_ticket(1, &s_t, tid);
        if (tk >= 544u) return;
        const int b  = (int)(tk / 136u);
        const int tt = (int)(tk % 136u);
        int it = (int)floorf((sqrtf(8.f * (float)tt + 1.f) - 1.f) * 0.5f);
        while ((it + 1) * (it + 2) / 2 <= tt) ++it;
        while (it * (it + 1) / 2 > tt) --it;
        const int jt = tt - it * (it + 1) / 2;

        float acc[4][4][4];
        gemm_1t_fixed<16>(g_Qh + ((size_t)b * SS + it * 128) * DD, DD,
                          g_Kh + ((size_t)b * SS + jt * 128) * DD, DD,
                          acc, sb, tid);

        __half* base = g_Ph + (size_t)b * SS * SS;
        float* rs = g_rs + (size_t)b * SS;

#pragma unroll
        for (int i = 0; i < 4; ++i) {
            const int r0 = it * 128 + wm * 64 + i * 16 + tg;
            const int r1 = r0 + 8;
            float sum0 = 0.f, sum1 = 0.f;
#pragma unroll
            for (int j = 0; j < 4; ++j) {
                const int c = jt * 128 + wn * 32 + j * 8 + t4 * 2;
                float e0 = (c     <= r0) ? __expf(acc[i][j][0] * scale) : 0.f;
                float e1 = (c + 1 <= r0) ? __expf(acc[i][j][1] * scale) : 0.f;
                float e2 = (c     <= r1) ? __expf(acc[i][j][2] * scale) : 0.f;
                float e3 = (c + 1 <= r1) ? __expf(acc[i][j][3] * scale) : 0.f;
                *(uint32_t*)(base + (size_t)r0 * SS + c) = packh2(e0, e1);
                *(uint32_t*)(base + (size_t)r1 * SS + c) = packh2(e2, e3);
                sum0 += e0 + e1;
                sum1 += e2 + e3;
            }
            sum0 += __shfl_xor_sync(0xffffffffu, sum0, 1);
            sum0 += __shfl_xor_sync(0xffffffffu, sum0, 2);
            sum1 += __shfl_xor_sync(0xffffffffu, sum1, 1);
            sum1 += __shfl_xor_sync(0xffffffffu, sum1, 2);
            if (t4 == 0) {
                atomicAdd(rs + r0, sum0);
                atomicAdd(rs + r1, sum1);
            }
        }
    }
}

// ---------------------------------------------------------------------------
// 3) PV, persistent with LPT ticket order: tickets 0..511,
//    it = 15 - (t>>5)  (heavy first), inner = t&31 -> (b, n0). grid NPERS
// ---------------------------------------------------------------------------
__global__ void __launch_bounds__(256, 2) pv_gemm(float* __restrict__ out)
{
    extern __shared__ char smem[];
    __shared__ unsigned s_t;
    const uint32_t sb = smem_u32(smem);
    const int tid = threadIdx.x, lane = tid & 31, w = tid >> 5;
    const int tg = lane >> 2, t4 = lane & 3;
    const int wm = w & 1, wn = w >> 1;

    for (;;) {
        const unsigned t = next_ticket(2, &s_t, tid);
        if (t >= 512u) return;
        const int it = 15 - (int)(t >> 5);   // heavy-first
        const int inner = t & 31;
        const int b = inner >> 3;
        const int n0 = (inner & 7) * 128;

        float acc[4][4][4];
        gemm_1t(g_Ph + ((size_t)b * SS + it * 128) * SS, SS,
                g_Vth + ((size_t)b * DD + n0) * SS, SS,
                (it + 1) * 2, acc, sb, tid);

#pragma unroll
        for (int i = 0; i < 4; ++i) {
            const int rr = it * 128 + wm * 64 + i * 16 + tg;
            const float inv0 = 1.f / g_rs[(size_t)b * SS + rr];
            const float inv1 = 1.f / g_rs[(size_t)b * SS + rr + 8];
            const size_t r = (size_t)b * SS + rr;
#pragma unroll
            for (int j = 0; j < 4; ++j) {
                const int c = n0 + wn * 32 + j * 8 + t4 * 2;
                *(float2*)(out + r * DD + c) =
                    make_float2(acc[i][j][0] * inv0, acc[i][j][1] * inv0);
                *(float2*)(out + (r + 8) * DD + c) =
                    make_float2(acc[i][j][2] * inv1, acc[i][j][3] * inv1);
            }
        }
    }
}

// ---------------------------------------------------------------------------
// Prep: x -> fp16 hi plane; zeroes g_rs and the work tickets.
// grid 8192, block 256
// ---------------------------------------------------------------------------
__global__ void __launch_bounds__(256) prep_x_kernel(const float* __restrict__ in)
{
    if (threadIdx.x == 0) g_rs[blockIdx.x] = 0.f;
    if (blockIdx.x == 0 && threadIdx.x < 3) g_tk[threadIdx.x] = 0u;
    size_t i = (size_t)blockIdx.x * 256 + threadIdx.x;
    float4 v = ((const float4*)in)[i];
    uint2 H;
    H.x = packh2(v.x, v.y);
    H.y = packh2(v.z, v.w);
    ((uint2*)g_xh)[i] = H;
}

// ---------------------------------------------------------------------------
// Prep: transpose + fp16 W (hi only). grid (32, 32, 3), block (32, 8)
// ---------------------------------------------------------------------------
__global__ void __launch_bounds__(256) prep_w_kernel(
    const float* __restrict__ WQ, const float* __restrict__ WK,
    const float* __restrict__ WV)
{
    __shared__ float t[32][33];
    const float* W = (blockIdx.z == 0) ? WQ : (blockIdx.z == 1) ? WK : WV;
    const int n0 = blockIdx.x * 32, k0 = blockIdx.y * 32;
    const int tx = threadIdx.x, ty = threadIdx.y;
#pragma unroll
    for (int j = 0; j < 32; j += 8)
        t[ty + j][tx] = W[(size_t)(k0 + ty + j) * DD + n0 + tx];
    __syncthreads();
    __half* oh = g_Wth + (size_t)blockIdx.z * DD * DD;
#pragma unroll
    for (int j = 0; j < 32; j += 8) {
        size_t o = (size_t)(n0 + ty + j) * DD + k0 + tx;
        oh[o] = __float2half_rn(t[tx][ty + j]);
    }
}

// ---------------------------------------------------------------------------
extern "C" void kernel_launch(void* const* d_in, const int* in_sizes, int n_in,
                              void* d_out, int out_size)
{
    (void)in_sizes; (void)n_in; (void)out_size;
    const float* x  = (const float*)d_in[0];
    const float* WQ = (const float*)d_in[1];
    const float* WK = (const float*)d_in[2];
    const float* WV = (const float*)d_in[3];
    float* out = (float*)d_out;

    cudaFuncSetAttribute(qkv_gemm,    cudaFuncAttributeMaxDynamicSharedMemorySize, SM_TOT);
    cudaFuncSetAttribute(scores_gemm, cudaFuncAttributeMaxDynamicSharedMemorySize, SM_TOT);
    cudaFuncSetAttribute(pv_gemm,     cudaFuncAttributeMaxDynamicSharedMemorySize, SM_TOT);

    prep_x_kernel<<<8192, 256>>>(x);
    prep_w_kernel<<<dim3(32, 32, 3), dim3(32, 8)>>>(WQ, WK, WV);
    qkv_gemm<<<NPERS, 256, SM_TOT>>>();
    scores_gemm<<<NPERS, 256, SM_TOT>>>();
    pv_gemm<<<NPERS, 256, SM_TOT>>>(out);
}

// round 17
// speedup vs baseline: 1.1665x; 1.1665x over previous
#include <cuda_runtime.h>
#include <cuda_fp16.h>
#include <math.h>
#include <stdint.h>

#define BB 4
#define SS 2048
#define DD 1024
#define MT (BB*SS)   // 8192

// ---------------------------------------------------------------------------
// Scratch (device globals) — all operands fp16 hi-plane only
// ---------------------------------------------------------------------------
__device__ __align__(16) __half g_xh [(size_t)MT*DD];                 // A of QKV
__device__ __align__(16) __half g_Wth[(size_t)3*DD*DD];               // B of QKV (transposed)
__device__ __align__(16) __half g_Qh [(size_t)MT*DD];                 // A of scores
__device__ __align__(16) __half g_Kh [(size_t)MT*DD];                 // B of scores
__device__ __align__(16) __half g_Vth[(size_t)BB*DD*SS];              // B of PV
__device__ __align__(16) __half g_Ph [(size_t)BB*SS*SS];              // Pexp (unnormalized)
__device__ __align__(16) float  g_rs [MT];                            // row sums

// ---------------------------------------------------------------------------
// Helpers
// ---------------------------------------------------------------------------
__device__ __forceinline__ uint32_t smem_u32(const void* p) {
    uint32_t a;
    asm("{ .reg .u64 t; cvta.to.shared.u64 t, %1; cvt.u32.u64 %0, t; }"
        : "=r"(a) : "l"(p));
    return a;
}

#define SWZ(o) ((uint32_t)(o) ^ ((((uint32_t)(o)) >> 3) & 0x70))

#define CP_ASYNC(dst, src) \
    asm volatile("cp.async.cg.shared.global [%0], [%1], 16;" \
                 :: "r"(dst), "l"(__cvta_generic_to_global(src)))
#define CP_COMMIT() asm volatile("cp.async.commit_group;")
#define CP_WAIT1()  asm volatile("cp.async.wait_group 1;")
#define CP_WAIT0()  asm volatile("cp.async.wait_group 0;")

#define LDM_X4(r, addr) \
    asm volatile("ldmatrix.sync.aligned.m8n8.x4.shared.b16 {%0,%1,%2,%3}, [%4];" \
        : "=r"((r)[0]), "=r"((r)[1]), "=r"((r)[2]), "=r"((r)[3]) : "r"(addr))

#define MMA_F16(d, a, b0v, b1v) \
    asm volatile("mma.sync.aligned.m16n8k16.row.col.f32.f16.f16.f32 " \
        "{%0,%1,%2,%3}, {%4,%5,%6,%7}, {%8,%9}, {%0,%1,%2,%3};" \
        : "+f"((d)[0]), "+f"((d)[1]), "+f"((d)[2]), "+f"((d)[3]) \
        : "r"((a)[0]), "r"((a)[1]), "r"((a)[2]), "r"((a)[3]), "r"(b0v), "r"(b1v))

__device__ __forceinline__ uint32_t packh2(float a, float b) {
    __half2 h = __floats2half2_rn(a, b);
    return *(uint32_t*)&h;
}

// ---------------------------------------------------------------------------
// SMEM: 1-term stage = A(16K)+B(16K) = 32KB x 3 stages = 96KB -> 2 CTAs/SM
// ---------------------------------------------------------------------------
#define OFF_A  0
#define OFF1_B 16384
#define STG1   32768
#define SM_TOT 98304

// transpose-staging (epilogue reuse): 128 rows x 130 half = 260B rows
#define TRROW 260
#define TRH   0

// ===========================================================================
// 1-term GEMM: acc += A*B, 3-stage pipeline, warp tile 64x32, CTA 128x128.
// ===========================================================================
__device__ __forceinline__ void load_chunk1(
    uint32_t stg,
    const __half* __restrict__ A, int lda,
    const __half* __restrict__ B, int ldb,
    int k0, int tid)
{
#pragma unroll
    for (int i = 0; i < 4; ++i) {
        int u = tid + i * 256, row = u >> 3, ch = u & 7;
        uint32_t off = SWZ(row * 128 + ch * 16);
        CP_ASYNC(stg + OFF_A  + off, A + (size_t)row * lda + k0 + ch * 8);
        CP_ASYNC(stg + OFF1_B + off, B + (size_t)row * ldb + k0 + ch * 8);
    }
}

__device__ __forceinline__ void compute_chunk1(
    uint32_t stg, int wm, int wn, int lane, float (&acc)[4][4][4])
{
    const int rsel = lane & 15;
    const int csel = lane >> 4;
#pragma unroll
    for (int ks = 0; ks < 4; ++ks) {
        const uint32_t cb = (ks * 2 + csel) * 16;
        uint32_t ah[4][4], bh[2][4];
#pragma unroll
        for (int j2 = 0; j2 < 2; ++j2)
            LDM_X4(bh[j2], stg + OFF1_B + SWZ((wn * 32 + j2 * 16 + rsel) * 128 + cb));
#pragma unroll
        for (int i = 0; i < 4; ++i)
            LDM_X4(ah[i], stg + OFF_A + SWZ((wm * 64 + i * 16 + rsel) * 128 + cb));
#pragma unroll
        for (int i = 0; i < 4; ++i)
#pragma unroll
            for (int j = 0; j < 4; ++j)
                MMA_F16(acc[i][j], ah[i], bh[j >> 1][j & 1], bh[j >> 1][(j & 1) + 2]);
    }
}

template <int NCH>
__device__ __forceinline__ void gemm_1t_fixed(
    const __half* __restrict__ A, int lda,
    const __half* __restrict__ B, int ldb,
    float (&acc)[4][4][4], uint32_t sb, int tid)
{
    const int lane = tid & 31, w = tid >> 5;
    const int wm = w & 1, wn = w >> 1;

#pragma unroll
    for (int i = 0; i < 4; ++i)
#pragma unroll
        for (int j = 0; j < 4; ++j)
#pragma unroll
            for (int q = 0; q < 4; ++q) acc[i][j][q] = 0.f;

    load_chunk1(sb + 0 * STG1, A, lda, B, ldb, 0, tid);
    CP_COMMIT();
    load_chunk1(sb + 1 * STG1, A, lda, B, ldb, 64, tid);
    CP_COMMIT();

#pragma unroll
    for (int c = 0; c < NCH; ++c) {
        if (c + 1 < NCH) { CP_WAIT1(); } else { CP_WAIT0(); }
        __syncthreads();
        if (c + 2 < NCH) {
            const int ns = (c + 2) % 3;
            load_chunk1(sb + ns * STG1, A, lda, B, ldb, (c + 2) * 64, tid);
            CP_COMMIT();
        }
        compute_chunk1(sb + (c % 3) * STG1, wm, wn, lane, acc);
    }
}

__device__ __forceinline__ void gemm_1t(
    const __half* __restrict__ A, int lda,
    const __half* __restrict__ B, int ldb,
    int nCh, float (&acc)[4][4][4], uint32_t sb, int tid)
{
    const int lane = tid & 31, w = tid >> 5;
    const int wm = w & 1, wn = w >> 1;

#pragma unroll
    for (int i = 0; i < 4; ++i)
#pragma unroll
        for (int j = 0; j < 4; ++j)
#pragma unroll
            for (int q = 0; q < 4; ++q) acc[i][j][q] = 0.f;

    load_chunk1(sb + 0 * STG1, A, lda, B, ldb, 0, tid);
    CP_COMMIT();
    load_chunk1(sb + 1 * STG1, A, lda, B, ldb, 64, tid);
    CP_COMMIT();

    int slot = 0;
    for (int c = 0; c < nCh; ++c) {
        if (c + 1 < nCh) { CP_WAIT1(); } else { CP_WAIT0(); }
        __syncthreads();
        if (c + 2 < nCh) {
            int ns = slot + 2; if (ns >= 3) ns -= 3;
            load_chunk1(sb + ns * STG1, A, lda, B, ldb, (c + 2) * 64, tid);
            CP_COMMIT();
        }
        compute_chunk1(sb + slot * STG1, wm, wn, lane, acc);
        if (++slot == 3) slot = 0;
    }
}

// ---------------------------------------------------------------------------
// 1) QKV GEMM (1-term): z=0->Q, z=1->K, z=2->V transposed (fused via smem).
//    grid (8, 64, 3)
// ---------------------------------------------------------------------------
__global__ void __launch_bounds__(256, 2) qkv_gemm()
{
    extern __shared__ char smem[];
    const uint32_t sb = smem_u32(smem);
    const int tid = threadIdx.x, lane = tid & 31, w = tid >> 5;
    const int z = blockIdx.z;
    const int n0 = blockIdx.x * 128;
    const int m0 = blockIdx.y * 128;

    float acc[4][4][4];
    gemm_1t_fixed<16>(g_xh + (size_t)m0 * DD, DD,
                      g_Wth + (size_t)z * DD * DD + (size_t)n0 * DD, DD,
                      acc, sb, tid);

    const int tg = lane >> 2, t4 = lane & 3;
    const int wm = w & 1, wn = w >> 1;

    if (z == 2) {
        // Fused V transpose (hi plane only).
        __syncthreads();
#pragma unroll
        for (int i = 0; i < 4; ++i) {
#pragma unroll
            for (int j = 0; j < 4; ++j) {
                const int rl = wm * 64 + i * 16 + tg;
                const int cl = wn * 32 + j * 8 + t4 * 2;
                *(uint32_t*)(smem + TRH + rl * TRROW + cl * 2) =
                    packh2(acc[i][j][0], acc[i][j][1]);
                *(uint32_t*)(smem + TRH + (rl + 8) * TRROW + cl * 2) =
                    packh2(acc[i][j][2], acc[i][j][3]);
            }
        }
        __syncthreads();
        const int b = m0 >> 11, s0r = m0 & 2047;
        const int d = tid >> 1, sh = tid & 1;
        __half* dstH = g_Vth + ((size_t)b * DD + n0 + d) * SS + s0r + sh * 64;
#pragma unroll
        for (int g = 0; g < 8; ++g) {
            uint32_t wh[4];
#pragma unroll
            for (int e = 0; e < 4; ++e) {
                const int s = sh * 64 + g * 8 + e * 2;
                uint32_t h0 = *(uint16_t*)(smem + TRH + s * TRROW + d * 2);
                uint32_t h1 = *(uint16_t*)(smem + TRH + (s + 1) * TRROW + d * 2);
                wh[e] = h0 | (h1 << 16);
            }
            *(uint4*)(dstH + g * 8) = make_uint4(wh[0], wh[1], wh[2], wh[3]);
        }
        return;
    }

    __half* dst = (z == 0) ? g_Qh : g_Kh;
#pragma unroll
    for (int i = 0; i < 4; ++i) {
#pragma unroll
        for (int j = 0; j < 4; ++j) {
            const int r = m0 + wm * 64 + i * 16 + tg;
            const int c = n0 + wn * 32 + j * 8 + t4 * 2;
            *(uint32_t*)(dst + (size_t)r * DD + c) =
                packh2(acc[i][j][0], acc[i][j][1]);
            *(uint32_t*)(dst + (size_t)(r + 8) * DD + c) =
                packh2(acc[i][j][2], acc[i][j][3]);
        }
    }
}

// ---------------------------------------------------------------------------
// 2) Scores+exp: Pexp = exp(scale * Q @ K^T) with causal mask, fp16 out,
//    per-row sums accumulated to g_rs via atomics. grid (136, 4)
// ---------------------------------------------------------------------------
__global__ void __launch_bounds__(256, 2) scores_gemm()
{
    const int t = blockIdx.x, b = blockIdx.y;
    int it = (int)floorf((sqrtf(8.f * (float)t + 1.f) - 1.f) * 0.5f);
    while ((it + 1) * (it + 2) / 2 <= t) ++it;
    while (it * (it + 1) / 2 > t) --it;
    const int jt = t - it * (it + 1) / 2;

    extern __shared__ char smem[];
    const uint32_t sb = smem_u32(smem);
    const int tid = threadIdx.x, lane = tid & 31, w = tid >> 5;

    float acc[4][4][4];
    gemm_1t_fixed<16>(g_Qh + ((size_t)b * SS + it * 128) * DD, DD,
                      g_Kh + ((size_t)b * SS + jt * 128) * DD, DD,
                      acc, sb, tid);

    const int tg = lane >> 2, t4 = lane & 3;
    const int wm = w & 1, wn = w >> 1;
    const float scale = 0.03125f;  // 1/sqrt(1024)
    __half* base = g_Ph + (size_t)b * SS * SS;
    float* rs = g_rs + (size_t)b * SS;

#pragma unroll
    for (int i = 0; i < 4; ++i) {
        const int r0 = it * 128 + wm * 64 + i * 16 + tg;
        const int r1 = r0 + 8;
        float sum0 = 0.f, sum1 = 0.f;
#pragma unroll
        for (int j = 0; j < 4; ++j) {
            const int c = jt * 128 + wn * 32 + j * 8 + t4 * 2;
            float e0 = (c     <= r0) ? __expf(acc[i][j][0] * scale) : 0.f;
            float e1 = (c + 1 <= r0) ? __expf(acc[i][j][1] * scale) : 0.f;
            float e2 = (c     <= r1) ? __expf(acc[i][j][2] * scale) : 0.f;
            float e3 = (c + 1 <= r1) ? __expf(acc[i][j][3] * scale) : 0.f;
            *(uint32_t*)(base + (size_t)r0 * SS + c) = packh2(e0, e1);
            *(uint32_t*)(base + (size_t)r1 * SS + c) = packh2(e2, e3);
            sum0 += e0 + e1;
            sum1 += e2 + e3;
        }
        sum0 += __shfl_xor_sync(0xffffffffu, sum0, 1);
        sum0 += __shfl_xor_sync(0xffffffffu, sum0, 2);
        sum1 += __shfl_xor_sync(0xffffffffu, sum1, 1);
        sum1 += __shfl_xor_sync(0xffffffffu, sum1, 2);
        if (t4 == 0) {
            atomicAdd(rs + r0, sum0);
            atomicAdd(rs + r1, sum1);
        }
    }
}

// ---------------------------------------------------------------------------
// 3) PV: O = (Pexp @ V) / rowsum. Heavy row-blocks first. grid (8, 16, 4)
// ---------------------------------------------------------------------------
__global__ void __launch_bounds__(256, 2) pv_gemm(float* __restrict__ out)
{
    extern __shared__ char smem[];
    const uint32_t sb = smem_u32(smem);
    const int tid = threadIdx.x, lane = tid & 31, w = tid >> 5;
    const int n0 = blockIdx.x * 128;
    const int it = 15 - blockIdx.y;   // heavy-first
    const int b = blockIdx.z;

    float acc[4][4][4];
    gemm_1t(g_Ph + ((size_t)b * SS + it * 128) * SS, SS,
            g_Vth + ((size_t)b * DD + n0) * SS, SS,
            (it + 1) * 2, acc, sb, tid);

    const int tg = lane >> 2, t4 = lane & 3;
    const int wm = w & 1, wn = w >> 1;
#pragma unroll
    for (int i = 0; i < 4; ++i) {
        const int rr = it * 128 + wm * 64 + i * 16 + tg;
        const float inv0 = 1.f / g_rs[(size_t)b * SS + rr];
        const float inv1 = 1.f / g_rs[(size_t)b * SS + rr + 8];
        const size_t r = (size_t)b * SS + rr;
#pragma unroll
        for (int j = 0; j < 4; ++j) {
            const int c = n0 + wn * 32 + j * 8 + t4 * 2;
            *(float2*)(out + r * DD + c) =
                make_float2(acc[i][j][0] * inv0, acc[i][j][1] * inv0);
            *(float2*)(out + (r + 8) * DD + c) =
                make_float2(acc[i][j][2] * inv1, acc[i][j][3] * inv1);
        }
    }
}

// ---------------------------------------------------------------------------
// Fused prep: blocks [0, 8192) convert x -> fp16 (+ zero g_rs);
//             blocks [8192, 8192+3072) transpose + fp16 W.
// grid 11264, block 256
// ---------------------------------------------------------------------------
__global__ void __launch_bounds__(256) prep_kernel(
    const float* __restrict__ x,
    const float* __restrict__ WQ, const float* __restrict__ WK,
    const float* __restrict__ WV)
{
    __shared__ float t[32][33];
    const int bid = blockIdx.x;
    const int tid = threadIdx.x;

    if (bid < 8192) {
        if (tid == 0) g_rs[bid] = 0.f;
        size_t i = (size_t)bid * 256 + tid;
        float4 v = ((const float4*)x)[i];
        uint2 H;
        H.x = packh2(v.x, v.y);
        H.y = packh2(v.z, v.w);
        ((uint2*)g_xh)[i] = H;
        return;
    }

    // W transpose: decode (nx, ky, z) from bid-8192 over 32x32x3
    const int wb = bid - 8192;
    const int z  = wb / 1024;
    const int r  = wb - z * 1024;
    const int nx = r & 31, ky = r >> 5;
    const float* W = (z == 0) ? WQ : (z == 1) ? WK : WV;
    const int n0 = nx * 32, k0 = ky * 32;
    const int tx = tid & 31, ty = tid >> 5;
#pragma unroll
    for (int j = 0; j < 32; j += 8)
        t[ty + j][tx] = W[(size_t)(k0 + ty + j) * DD + n0 + tx];
    __syncthreads();
    __half* oh = g_Wth + (size_t)z * DD * DD;
#pragma unroll
    for (int j = 0; j < 32; j += 8) {
        size_t o = (size_t)(n0 + ty + j) * DD + k0 + tx;
        oh[o] = __float2half_rn(t[tx][ty + j]);
    }
}

// ---------------------------------------------------------------------------
extern "C" void kernel_launch(void* const* d_in, const int* in_sizes, int n_in,
                              void* d_out, int out_size)
{
    (void)in_sizes; (void)n_in; (void)out_size;
    const float* x  = (const float*)d_in[0];
    const float* WQ = (const float*)d_in[1];
    const float* WK = (const float*)d_in[2];
    const float* WV = (const float*)d_in[3];
    float* out = (float*)d_out;

    cudaFuncSetAttribute(qkv_gemm,    cudaFuncAttributeMaxDynamicSharedMemorySize, SM_TOT);
    cudaFuncSetAttribute(scores_gemm, cudaFuncAttributeMaxDynamicSharedMemorySize, SM_TOT);
    cudaFuncSetAttribute(pv_gemm,     cudaFuncAttributeMaxDynamicSharedMemorySize, SM_TOT);

    prep_kernel<<<11264, 256>>>(x, WQ, WK, WV);
    qkv_gemm<<<dim3(8, 64, 3), 256, SM_TOT>>>();
    scores_gemm<<<dim3(136, 4), 256, SM_TOT>>>();
    pv_gemm<<<dim3(8, 16, 4), 256, SM_TOT>>>(out);
}